// round 10
// baseline (speedup 1.0000x reference)
#include <cuda_runtime.h>
#include <mma.h>
#include <cstdint>

using namespace nvcuda;

#define N_  4
#define C_  128
#define H_  128
#define W_  128
#define OC  8
#define OH  256
#define OW  256
#define HW  (H_*W_)
#define NT  72        // 8 outputs x 9 taps (padded to 80 in S)
#define NTP 80

// S[n][t][hw] pointwise GEMM result, t = tap*8 + o  (t in [0,80), rows 72..79 pad)
__device__ float g_S[N_ * NTP * HW];
// off[n][o][h][w]
__device__ float g_off[N_ * OC * HW];

// ---------------------------------------------------------------------------
// Kernel 1: pointwise GEMM  S[t, px] = sum_c W[t,c] * x[c, px]   via wmma tf32.
// Per block: one (n, 128-px tile). A = x[c][px] as col-major (px x c),
// B = Wt[c][t] row-major, C stored col-major directly to S[t][px] (ldm=HW).
// Grid 512 = 4n x 128 tiles, 256 threads (8 warps: warp w = px rows 16w..16w+15).
// ---------------------------------------------------------------------------
#define SM_XT_F  0                    // 128c x 128px floats
#define SM_B_F   (128*128)            // 128c x 80t floats
#define SM_TOT_B ((128*128 + 128*NTP) * 4)

__global__ __launch_bounds__(256) void conv_gemm_kernel(
    const float* __restrict__ x,
    const float* __restrict__ wt)    // [o][c][3][3]
{
    extern __shared__ float sm[];
    float* xt = sm + SM_XT_F;        // xt[c*128 + px]
    float* Wt = sm + SM_B_F;         // Wt[c*NTP + t]

    const int tid = threadIdx.x;
    const int bid = blockIdx.x;
    const int n   = bid >> 7;
    const int px0 = (bid & 127) * 128;

    // Stage B: Wt[c][t] = wt[o][c][tap], t = tap*8+o; pad t>=72 with 0
    for (int i = tid; i < 128*NTP; i += 256) {
        int c = i / NTP, t = i - c*NTP;
        float v = 0.f;
        if (t < NT) v = wt[(((size_t)(t & 7))*C_ + c)*9 + (t >> 3)];
        Wt[i] = v;
    }

    // Stage A: x[c][px0..px0+128]
    const float* xn = x + (size_t)n*C_*HW + px0;
    for (int i = tid; i < 128*32; i += 256) {
        int c = i >> 5, p4 = (i & 31)*4;
        *reinterpret_cast<float4*>(xt + c*128 + p4) =
            *reinterpret_cast<const float4*>(xn + (size_t)c*HW + p4);
    }
    __syncthreads();

    const int wid = tid >> 5;        // warp: px rows [16*wid, 16*wid+16)

    wmma::fragment<wmma::accumulator, 16, 16, 8, float> acc[5];
#pragma unroll
    for (int tt = 0; tt < 5; tt++) wmma::fill_fragment(acc[tt], 0.f);

#pragma unroll
    for (int k = 0; k < 16; k++) {
        wmma::fragment<wmma::matrix_a, 16, 16, 8, wmma::precision::tf32, wmma::col_major> a;
        wmma::load_matrix_sync(a, xt + (k*8)*128 + 16*wid, 128);
#pragma unroll
        for (int e = 0; e < a.num_elements; e++)
            a.x[e] = wmma::__float_to_tf32(a.x[e]);
#pragma unroll
        for (int tt = 0; tt < 5; tt++) {
            wmma::fragment<wmma::matrix_b, 16, 16, 8, wmma::precision::tf32, wmma::row_major> b;
            wmma::load_matrix_sync(b, Wt + (k*8)*NTP + tt*16, NTP);
#pragma unroll
            for (int e = 0; e < b.num_elements; e++)
                b.x[e] = wmma::__float_to_tf32(b.x[e]);
            wmma::mma_sync(acc[tt], a, b, acc[tt]);
        }
    }

    // Store C col-major straight into S[t][px]: col stride = HW
    float* Sp = g_S + (size_t)n*NTP*HW + px0 + 16*wid;
#pragma unroll
    for (int tt = 0; tt < 5; tt++)
        wmma::store_matrix_sync(Sp + (size_t)(tt*16)*HW, acc[tt], HW, wmma::mem_col_major);
}

// ---------------------------------------------------------------------------
// Kernel 2: shift-add epilogue  off[o,h,w] = bias[o] + sum_tap S[tap*8+o, h+ky-1, w+kx-1]
// Grid 512 = (n, h); 256 threads = 128 w x 2 o-groups (4 o each).
// ---------------------------------------------------------------------------
__global__ __launch_bounds__(256) void shift_add_kernel(
    const float* __restrict__ bs)
{
    const int b = blockIdx.x;
    const int n = b >> 7;
    const int h = b & (H_-1);
    const int tid = threadIdx.x;
    const int w  = tid & 127;
    const int og = (tid >> 7) * 4;

    const float* Sn = g_S + (size_t)n*NTP*HW;

#pragma unroll
    for (int oo = 0; oo < 4; oo++) {
        const int o = og + oo;
        float s = __ldg(&bs[o]);
#pragma unroll
        for (int ky = 0; ky < 3; ky++) {
            const int hh = h + ky - 1;
            if ((unsigned)hh >= H_) continue;
#pragma unroll
            for (int kx = 0; kx < 3; kx++) {
                const int ww = w + kx - 1;
                if ((unsigned)ww >= W_) continue;
                const int t = (ky*3 + kx)*8 + o;
                s += Sn[(size_t)t*HW + hh*W_ + ww];
            }
        }
        g_off[(((size_t)n*OC + o)*H_ + h)*W_ + w] = s;
    }
}

// ---------------------------------------------------------------------------
// Kernel 3: bilinear sampling + pixel shuffle (r3 measured-best gather).
// One block per (n, h, kh): 256 threads, tid = w*2 + kw.
// ---------------------------------------------------------------------------
__global__ __launch_bounds__(256) void sample_kernel(
    const float* __restrict__ x,
    float* __restrict__ out)
{
    __shared__ float soff[4][W_];

    const int b  = blockIdx.x;
    const int kh = b & 1;
    const int h  = (b >> 1) & (H_-1);
    const int n  = b >> 8;
    const int tid = threadIdx.x;

    for (int i = tid; i < 4*W_; i += 256) {
        int j  = i >> 7;
        int ww = i & (W_-1);
        int o  = (kh*2 + (j >> 1))*2 + (j & 1);
        soff[j][ww] = g_off[(((size_t)n*OC + o)*H_ + h)*W_ + ww];
    }
    __syncthreads();

    const int kw = tid & 1;
    const int w  = tid >> 1;

    float sy = (float)h + soff[kw*2    ][w];
    float sx = (float)w + soff[kw*2 + 1][w];
    float y0f = floorf(sy), x0f = floorf(sx);
    int   y0 = (int)y0f,   x0 = (int)x0f;
    float fy = sy - y0f,   fx = sx - x0f;

    float cw[4];
    cw[0] = (1.f - fy) * (1.f - fx);
    cw[1] = (1.f - fy) * fx;
    cw[2] = fy * (1.f - fx);
    cw[3] = fy * fx;
    int ci[4];
#pragma unroll
    for (int k = 0; k < 4; k++) {
        int yi = y0 + (k >> 1);
        int xi = x0 + (k & 1);
        bool valid = ((unsigned)yi < H_) && ((unsigned)xi < W_);
        int yc = min(max(yi, 0), H_-1);
        int xc = min(max(xi, 0), W_-1);
        ci[k] = yc*W_ + xc;
        if (!valid) cw[k] = 0.f;
    }

    const float* xp = x + (size_t)n*C_*HW;
    float* op = out + ((size_t)n*C_)*OH*OW + (size_t)(2*h + kh)*OW + (2*w + kw);

#pragma unroll 2
    for (int c = 0; c < C_; c++) {
        float v0 = __ldg(xp + ci[0]);
        float v1 = __ldg(xp + ci[1]);
        float v2 = __ldg(xp + ci[2]);
        float v3 = __ldg(xp + ci[3]);
        float r = v0*cw[0];
        r = fmaf(v1, cw[1], r);
        r = fmaf(v2, cw[2], r);
        r = fmaf(v3, cw[3], r);
        *op = r;
        xp += HW;
        op += OH*OW;
    }
}

// ---------------------------------------------------------------------------
extern "C" void kernel_launch(void* const* d_in, const int* in_sizes, int n_in,
                              void* d_out, int out_size)
{
    const float* x  = (const float*)d_in[0];
    const float* wt = (const float*)d_in[1];
    const float* bs = (const float*)d_in[2];
    float* out = (float*)d_out;

    cudaFuncSetAttribute(conv_gemm_kernel,
                         cudaFuncAttributeMaxDynamicSharedMemorySize, SM_TOT_B);

    conv_gemm_kernel<<<512, 256, SM_TOT_B>>>(x, wt);
    shift_add_kernel<<<512, 256>>>(bs);
    sample_kernel<<<N_*H_*2, 256>>>(x, out);
}

// round 11
// speedup vs baseline: 1.1487x; 1.1487x over previous
#include <cuda_runtime.h>
#include <mma.h>
#include <cstdint>

using namespace nvcuda;

#define N_  4
#define C_  128
#define H_  128
#define W_  128
#define OC  8
#define OH  256
#define OW  256
#define HW  (H_*W_)
#define NT  72
#define NTP 80

// S[n][t][hw], t = tap*8 + o  (t in [0,80), rows 72..79 pad)
__device__ float g_S[N_ * NTP * HW];
// off[n][o][h][w]
__device__ float g_off[N_ * OC * HW];

__device__ __forceinline__ float to_tf32(float f) {
    float r;
    asm("cvt.rna.tf32.f32 %0, %1;" : "=f"(r) : "f"(f));
    return r;
}

// ---------------------------------------------------------------------------
// Kernel 1: pointwise GEMM S[t,px] = sum_c W[t,c]*x[c,px], wmma tf32,
// register-blocked 2x5 per warp. Block = 256 thr / 8 warps, tile = 256px x 80t,
// K in 2 stages of 64 channels (x buffer reused). Values pre-rounded to tf32
// in smem so no per-fragment conversion. Grid 256 = 4n x 64 tiles.
// ---------------------------------------------------------------------------
#define PXT  256
#define SM_XT_F  0                          // 64c x 256px
#define SM_B_F   (64*PXT)                   // 128c x 80t
#define SM_TOT_B ((64*PXT + 128*NTP) * 4)   // 104 KB

__global__ __launch_bounds__(256, 2) void conv_gemm_kernel(
    const float* __restrict__ x,
    const float* __restrict__ wt)    // [o][c][3][3]
{
    extern __shared__ float sm[];
    float* xt = sm + SM_XT_F;        // xt[c][px] c in [0,64) local
    float* Wt = sm + SM_B_F;         // Wt[c][t]  c in [0,128)

    const int tid = threadIdx.x;
    const int bid = blockIdx.x;
    const int n   = bid >> 6;
    const int px0 = (bid & 63) * PXT;
    const int wid = tid >> 5;        // warp: px rows [32*wid, 32*wid+32)

    // Stage B once (pre-rounded): Wt[c][t] = wt[o][c][tap], t = tap*8+o
    for (int i = tid; i < 128*NTP; i += 256) {
        int c = i / NTP, t = i - c*NTP;
        float v = 0.f;
        if (t < NT) v = to_tf32(wt[(((size_t)(t & 7))*C_ + c)*9 + (t >> 3)]);
        Wt[i] = v;
    }

    wmma::fragment<wmma::accumulator, 16, 16, 8, float> acc[2][5];
#pragma unroll
    for (int i = 0; i < 2; i++)
#pragma unroll
        for (int tt = 0; tt < 5; tt++) wmma::fill_fragment(acc[i][tt], 0.f);

    const float* xn = x + (size_t)n*C_*HW + px0;

    for (int s = 0; s < 2; s++) {
        __syncthreads();   // xt reuse (and B ready on s=0)
        // Stage 64 channels of x (pre-rounded to tf32)
        for (int i = tid; i < 64*(PXT/4); i += 256) {
            int c = i >> 6, p4 = (i & 63)*4;
            float4 v = *reinterpret_cast<const float4*>(xn + (size_t)(s*64 + c)*HW + p4);
            v.x = to_tf32(v.x); v.y = to_tf32(v.y);
            v.z = to_tf32(v.z); v.w = to_tf32(v.w);
            *reinterpret_cast<float4*>(xt + c*PXT + p4) = v;
        }
        __syncthreads();

#pragma unroll
        for (int kl = 0; kl < 8; kl++) {
            wmma::fragment<wmma::matrix_a, 16, 16, 8, wmma::precision::tf32, wmma::col_major> a0, a1;
            wmma::load_matrix_sync(a0, xt + (kl*8)*PXT + 32*wid,      PXT);
            wmma::load_matrix_sync(a1, xt + (kl*8)*PXT + 32*wid + 16, PXT);
#pragma unroll
            for (int tt = 0; tt < 5; tt++) {
                wmma::fragment<wmma::matrix_b, 16, 16, 8, wmma::precision::tf32, wmma::row_major> b;
                wmma::load_matrix_sync(b, Wt + (s*64 + kl*8)*NTP + tt*16, NTP);
                wmma::mma_sync(acc[0][tt], a0, b, acc[0][tt]);
                wmma::mma_sync(acc[1][tt], a1, b, acc[1][tt]);
            }
        }
    }

    // Store C col-major straight into S[t][px]: col stride = HW
    float* Sp = g_S + (size_t)n*NTP*HW + px0 + 32*wid;
#pragma unroll
    for (int i = 0; i < 2; i++)
#pragma unroll
        for (int tt = 0; tt < 5; tt++)
            wmma::store_matrix_sync(Sp + i*16 + (size_t)(tt*16)*HW, acc[i][tt],
                                    HW, wmma::mem_col_major);
}

// ---------------------------------------------------------------------------
// Kernel 2: shift-add epilogue  off[o,h,w] = bias[o] + sum_tap S[tap*8+o, h+ky-1, w+kx-1]
// ---------------------------------------------------------------------------
__global__ __launch_bounds__(256) void shift_add_kernel(
    const float* __restrict__ bs)
{
    const int b = blockIdx.x;
    const int n = b >> 7;
    const int h = b & (H_-1);
    const int tid = threadIdx.x;
    const int w  = tid & 127;
    const int og = (tid >> 7) * 4;

    const float* Sn = g_S + (size_t)n*NTP*HW;

#pragma unroll
    for (int oo = 0; oo < 4; oo++) {
        const int o = og + oo;
        float s = __ldg(&bs[o]);
#pragma unroll
        for (int ky = 0; ky < 3; ky++) {
            const int hh = h + ky - 1;
            if ((unsigned)hh >= H_) continue;
#pragma unroll
            for (int kx = 0; kx < 3; kx++) {
                const int ww = w + kx - 1;
                if ((unsigned)ww >= W_) continue;
                const int t = (ky*3 + kx)*8 + o;
                s += Sn[(size_t)t*HW + hh*W_ + ww];
            }
        }
        g_off[(((size_t)n*OC + o)*H_ + h)*W_ + w] = s;
    }
}

// ---------------------------------------------------------------------------
// Kernel 3: bilinear sampling + pixel shuffle (measured-best gather).
// ---------------------------------------------------------------------------
__global__ __launch_bounds__(256) void sample_kernel(
    const float* __restrict__ x,
    float* __restrict__ out)
{
    __shared__ float soff[4][W_];

    const int b  = blockIdx.x;
    const int kh = b & 1;
    const int h  = (b >> 1) & (H_-1);
    const int n  = b >> 8;
    const int tid = threadIdx.x;

    for (int i = tid; i < 4*W_; i += 256) {
        int j  = i >> 7;
        int ww = i & (W_-1);
        int o  = (kh*2 + (j >> 1))*2 + (j & 1);
        soff[j][ww] = g_off[(((size_t)n*OC + o)*H_ + h)*W_ + ww];
    }
    __syncthreads();

    const int kw = tid & 1;
    const int w  = tid >> 1;

    float sy = (float)h + soff[kw*2    ][w];
    float sx = (float)w + soff[kw*2 + 1][w];
    float y0f = floorf(sy), x0f = floorf(sx);
    int   y0 = (int)y0f,   x0 = (int)x0f;
    float fy = sy - y0f,   fx = sx - x0f;

    float cw[4];
    cw[0] = (1.f - fy) * (1.f - fx);
    cw[1] = (1.f - fy) * fx;
    cw[2] = fy * (1.f - fx);
    cw[3] = fy * fx;
    int ci[4];
#pragma unroll
    for (int k = 0; k < 4; k++) {
        int yi = y0 + (k >> 1);
        int xi = x0 + (k & 1);
        bool valid = ((unsigned)yi < H_) && ((unsigned)xi < W_);
        int yc = min(max(yi, 0), H_-1);
        int xc = min(max(xi, 0), W_-1);
        ci[k] = yc*W_ + xc;
        if (!valid) cw[k] = 0.f;
    }

    const float* xp = x + (size_t)n*C_*HW;
    float* op = out + ((size_t)n*C_)*OH*OW + (size_t)(2*h + kh)*OW + (2*w + kw);

#pragma unroll 2
    for (int c = 0; c < C_; c++) {
        float v0 = __ldg(xp + ci[0]);
        float v1 = __ldg(xp + ci[1]);
        float v2 = __ldg(xp + ci[2]);
        float v3 = __ldg(xp + ci[3]);
        float r = v0*cw[0];
        r = fmaf(v1, cw[1], r);
        r = fmaf(v2, cw[2], r);
        r = fmaf(v3, cw[3], r);
        *op = r;
        xp += HW;
        op += OH*OW;
    }
}

// ---------------------------------------------------------------------------
extern "C" void kernel_launch(void* const* d_in, const int* in_sizes, int n_in,
                              void* d_out, int out_size)
{
    const float* x  = (const float*)d_in[0];
    const float* wt = (const float*)d_in[1];
    const float* bs = (const float*)d_in[2];
    float* out = (float*)d_out;

    cudaFuncSetAttribute(conv_gemm_kernel,
                         cudaFuncAttributeMaxDynamicSharedMemorySize, SM_TOT_B);

    conv_gemm_kernel<<<256, 256, SM_TOT_B>>>(x, wt);
    shift_add_kernel<<<512, 256>>>(bs);
    sample_kernel<<<N_*H_*2, 256>>>(x, out);
}